// round 12
// baseline (speedup 1.0000x reference)
#include <cuda_runtime.h>
#include <cuda_bf16.h>
#include <cstdint>

#define Bz   32
#define NV   12000
#define NT   20000
#define N1c  4000
#define N2c  1000
#define N12c 5000
#define KKc  20000
#define KC   625            // 32-wide k-chunks (625*32 = 20000 exactly)

// GEMM1: 32 m-tiles (4096 rows), Ksplit 9 (70 chunks/split, last 65)
#define MT1 32
#define MR1 4096
#define KS1 9
#define CPS1 70
// GEMM2: 40 m-tiles (5120 rows), Ksplit 7 (90 chunks/split, last 85)
#define MT2 40
#define MR2 5120
#define KS2 7
#define CPS2 90

#define BPITCH 40   // bf16 elems per B smem row (80B, conflict-free ldmatrix)

// ---------------- device scratch (static; no allocations) ----------------
__device__ float  g_px[NV * Bz];            // [v*32 + b]
__device__ float  g_py[NV * Bz];
__device__ float  g_pz[NV * Bz];
__device__ __nv_bfloat16 g_Bh[NT * Bz];     // B hi split, rows k-permuted per 16
__device__ __nv_bfloat16 g_Bl[NT * Bz];     // B lo split
__device__ float  g_cy[N1c * Bz];           // coeffy [i*32 + b]
__device__ float  g_cz[N12c * Bz];
__device__ float  g_Pf[(size_t)KS1 * MR1 * 32];  // K-split partial slab
__device__ float2 g_volP[1250 * 16];
__device__ float  g_volcP[1250];
__device__ float  g_a[Bz];
__device__ float  g_sy[Bz];
__device__ float  g_sz[Bz];

// k-permutation within each 16-group: physical pair q -> logical pair
// (q even ? q/2 : 4 + q/2). Makes A float4 halves = MMA a01/a45 directly.
__device__ __forceinline__ int kperm(int p) {
    int q = p >> 1;
    int lp = (q & 1) ? 4 + (q >> 1) : (q >> 1);
    return lp * 2 + (p & 1);
}

// ---------------- K0: build SoA points (batch-fastest) + zero sums --------
__global__ void k_init(const float* __restrict__ x, const float* __restrict__ y,
                       const float* __restrict__ p0) {
    int u = blockIdx.x * 256 + threadIdx.x;
    if (u < 64) { if (u < 32) g_sy[u] = 0.f; else g_sz[u - 32] = 0.f; }
    if (u >= NV * Bz) return;
    int v = u >> 5, b = u & 31;
    float px, py, pz;
    if (v < N1c) {
        const float* xb = x + (size_t)b * (N1c * 3) + v * 3;
        px = xb[0]; py = xb[1]; pz = xb[2];
    } else if (v < N12c) {
        int j = v - N1c;
        const float* yb = y + (size_t)b * (N2c * 2) + j * 2;
        px = yb[0]; pz = yb[1]; py = p0[v * 3 + 1];
    } else {
        px = p0[v * 3]; py = p0[v * 3 + 1]; pz = p0[v * 3 + 2];
    }
    g_px[u] = px; g_py[u] = py; g_pz[u] = pz;
}

// helper: split a pair of floats into bf16 hi/lo packed words
__device__ __forceinline__ void split2(float f0, float f1, uint32_t& hw, uint32_t& lw) {
    __nv_bfloat162 h = __floats2bfloat162_rn(f0, f1);
    float r0 = f0 - __bfloat162float(h.x);
    float r1 = f1 - __bfloat162float(h.y);
    __nv_bfloat162 l = __floats2bfloat162_rn(r0, r1);
    hw = *(uint32_t*)&h; lw = *(uint32_t*)&l;
}

// ---------------- K1: per-triangle dets -> bf16-split B (permuted rows) ---
// phase 1 reads py WITH the rank-1 y-correction applied on the fly
__global__ void k_det(const int* __restrict__ tri, const float* __restrict__ p0,
                      int phase) {
    __shared__ float2 sv[16];
    __shared__ float  sc;
    int tid = threadIdx.x;
    if (phase == 0) {
        if (tid < 16) sv[tid] = make_float2(0.f, 0.f);
        if (tid == 0) sc = 0.f;
        __syncthreads();
    }
    int u = blockIdx.x * 256 + tid;
    int t = u >> 4, b2 = u & 15;
    if (t < NT) {
        int v0 = tri[t * 3], v1 = tri[t * 3 + 1], v2 = tri[t * 3 + 2];
        const float2* PX = (const float2*)g_px;
        const float2* PY = (const float2*)g_py;
        const float2* PZ = (const float2*)g_pz;
        float2 x0 = PX[v0 * 16 + b2], x1 = PX[v1 * 16 + b2], x2 = PX[v2 * 16 + b2];
        float2 d;
        if (phase == 0) {
            float2 z0 = PZ[v0 * 16 + b2], z1 = PZ[v1 * 16 + b2], z2 = PZ[v2 * 16 + b2];
            float2 y0 = PY[v0 * 16 + b2], y1 = PY[v1 * 16 + b2], y2 = PY[v2 * 16 + b2];
            d.x = ((x0.x - x1.x) * (z2.x - z1.x) - (z0.x - z1.x) * (x2.x - x1.x)) * (1.f / 6.f);
            d.y = ((x0.y - x1.y) * (z2.y - z1.y) - (z0.y - z1.y) * (x2.y - x1.y)) * (1.f / 6.f);
            atomicAdd(&sv[b2].x, (y0.x + y1.x + y2.x) * d.x);
            atomicAdd(&sv[b2].y, (y0.y + y1.y + y2.y) * d.y);
            if (b2 == 0) {
                float X0 = p0[v0 * 3], Y0 = p0[v0 * 3 + 1], Z0 = p0[v0 * 3 + 2];
                float X1 = p0[v1 * 3], Y1 = p0[v1 * 3 + 1], Z1 = p0[v1 * 3 + 2];
                float X2 = p0[v2 * 3], Y2 = p0[v2 * 3 + 1], Z2 = p0[v2 * 3 + 2];
                float d0 = ((X0 - X1) * (Z2 - Z1) - (Z0 - Z1) * (X2 - X1)) * (1.f / 6.f);
                atomicAdd(&sc, (Y0 + Y1 + Y2) * d0);
            }
        } else {
            float2 av = ((const float2*)g_a)[b2];
            float2 sy = ((const float2*)g_sy)[b2];
            float2 rat = make_float2(av.x / sy.x, av.y / sy.y);
            float2 y0 = PY[v0 * 16 + b2], y1 = PY[v1 * 16 + b2], y2 = PY[v2 * 16 + b2];
            if (v0 < N1c) { float2 c = *(const float2*)(g_cy + v0 * 32 + 2 * b2);
                            y0.x += c.x * rat.x; y0.y += c.y * rat.y; }
            if (v1 < N1c) { float2 c = *(const float2*)(g_cy + v1 * 32 + 2 * b2);
                            y1.x += c.x * rat.x; y1.y += c.y * rat.y; }
            if (v2 < N1c) { float2 c = *(const float2*)(g_cy + v2 * 32 + 2 * b2);
                            y2.x += c.x * rat.x; y2.y += c.y * rat.y; }
            d.x = ((x0.x - x2.x) * (y1.x - y2.x) - (y0.x - y2.x) * (x1.x - x2.x)) * (1.f / 6.f);
            d.y = ((x0.y - x2.y) * (y1.y - y2.y) - (y0.y - y2.y) * (x1.y - x2.y)) * (1.f / 6.f);
        }
        uint32_t hw, lw;
        split2(d.x, d.y, hw, lw);
        int tp = (t & ~15) | kperm(t & 15);   // permuted row for GEMM
        *(uint32_t*)(g_Bh + tp * 32 + 2 * b2) = hw;
        *(uint32_t*)(g_Bl + tp * 32 + 2 * b2) = lw;
    }
    if (phase == 0) {
        __syncthreads();
        if (tid < 16) g_volP[blockIdx.x * 16 + tid] = sv[tid];
        if (tid == 0) g_volcP[blockIdx.x] = sc;
    }
}

// ---------------- K2: reduce volume partials -> a[b] ----------------------
__global__ void k_a() {
    __shared__ float2 red[256];
    __shared__ float  redc[256];
    int tid = threadIdx.x;
    int b2 = tid & 15, r = tid >> 4;
    float2 s = make_float2(0.f, 0.f);
    for (int j = r; j < 1250; j += 16) {
        float2 v = g_volP[j * 16 + b2]; s.x += v.x; s.y += v.y;
    }
    red[tid] = s;
    float c = 0.f;
    for (int j = tid; j < 1250; j += 256) c += g_volcP[j];
    redc[tid] = c;
    __syncthreads();
    for (int h = 8; h > 0; h >>= 1) {
        if (r < h) { red[tid].x += red[tid + h * 16].x; red[tid].y += red[tid + h * 16].y; }
        __syncthreads();
    }
    for (int h = 128; h > 0; h >>= 1) {
        if (tid < h) redc[tid] += redc[tid + h];
        __syncthreads();
    }
    if (tid < 32) {
        float volc = redc[0];
        float2 vb = red[tid >> 1];
        float volb = (tid & 1) ? vb.y : vb.x;
        g_a[tid] = 0.5f * (volc - volb);
    }
}

// ------- tensor-core GEMM: A LDG.128 2-deep, B 8-slab single-sync ring ----
#define LDSM4T(r, addr) \
    asm volatile("ldmatrix.sync.aligned.m8n8.x4.trans.shared.b16 {%0,%1,%2,%3}, [%4];" \
        : "=r"((r)[0]), "=r"((r)[1]), "=r"((r)[2]), "=r"((r)[3]) : "r"(addr))
#define MMABF16(dd, aa, bb) \
    asm volatile("mma.sync.aligned.m16n8k16.row.col.f32.bf16.bf16.f32 " \
        "{%0,%1,%2,%3}, {%4,%5,%6,%7}, {%8,%9}, {%0,%1,%2,%3};" \
        : "+f"((dd)[0]), "+f"((dd)[1]), "+f"((dd)[2]), "+f"((dd)[3]) \
        : "r"((aa)[0]), "r"((aa)[1]), "r"((aa)[2]), "r"((aa)[3]), \
          "r"((bb)[0]), "r"((bb)[1]))

__global__ void __launch_bounds__(256, 2)
k_gemm_tc(const float* __restrict__ A, int M, int Mrows, int cps) {
    __shared__ __align__(16) __nv_bfloat16 Bhs[8][32 * BPITCH];
    __shared__ __align__(16) __nv_bfloat16 Bls[8][32 * BPITCH];

    int tid = threadIdx.x;
    int lane = tid & 31, w = tid >> 5;      // 8 warps, each owns m16 rows
    int g = lane >> 2, t4 = lane & 3;
    int ibase = blockIdx.x * 128;
    int c0 = blockIdx.y * cps;
    int c1 = min(KC, c0 + cps);

    int row0 = ibase + w * 16 + g;
    bool v0 = row0 < M, v8 = (row0 + 8) < M;
    const float* A0 = A + (size_t)row0 * KKc + t4 * 4;
    const float* A8 = A0 + (size_t)8 * KKc;

    int bk = tid >> 3, bn = (tid & 7) * 4;  // B staging: 32 rows x 32 cols
    const size_t bOff = (size_t)bk * 32 + bn;

    // Two A chunk buffers, parity-static (selected by compile-time j&1).
    float4 arA[2][2], arB[2][2];            // [row r][kk]
    uint2 bhr[4], blr[4];
    const float4 z4 = make_float4(0.f, 0.f, 0.f, 0.f);

#define LOADA(buf, c) do { \
        int _kb = (c) * 32; \
        buf[0][0] = v0 ? *(const float4*)(A0 + _kb)      : z4; \
        buf[0][1] = v0 ? *(const float4*)(A0 + _kb + 16) : z4; \
        buf[1][0] = v8 ? *(const float4*)(A8 + _kb)      : z4; \
        buf[1][1] = v8 ? *(const float4*)(A8 + _kb + 16) : z4; \
    } while (0)

    // prefetch A chunks c0 (parity 0) and c0+1 (parity 1)
    LOADA(arA, c0);
    if (c0 + 1 < c1) LOADA(arB, c0 + 1);
    // prefetch B group [c0, c0+4)
#pragma unroll
    for (int j = 0; j < 4; j++) {
        int c = c0 + j;
        if (c < c1) {
            bhr[j] = *(const uint2*)(g_Bh + (size_t)c * 1024 + bOff);
            blr[j] = *(const uint2*)(g_Bl + (size_t)c * 1024 + bOff);
        }
    }

    float d[4][4];
#pragma unroll
    for (int nt = 0; nt < 4; nt++)
#pragma unroll
        for (int q = 0; q < 4; q++) d[nt][q] = 0.f;

    int gi = 0;
    for (int cb = c0; cb < c1; cb += 4, gi ^= 1) {
        int sbase = gi * 4;                 // alternating 4-slab half
        // stage this group's B (registers -> smem), single barrier
#pragma unroll
        for (int j = 0; j < 4; j++)
            if (cb + j < c1) {
                *(uint2*)(&Bhs[sbase + j][bk * BPITCH + bn]) = bhr[j];
                *(uint2*)(&Bls[sbase + j][bk * BPITCH + bn]) = blr[j];
            }
        __syncthreads();
        // prefetch next B group (flies during ~4 chunks of compute)
#pragma unroll
        for (int j = 0; j < 4; j++) {
            int c = cb + 4 + j;
            if (c < c1) {
                bhr[j] = *(const uint2*)(g_Bh + (size_t)c * 1024 + bOff);
                blr[j] = *(const uint2*)(g_Bl + (size_t)c * 1024 + bOff);
            }
        }
#pragma unroll
        for (int j = 0; j < 4; j++) {
            int c = cb + j;
            if (c >= c1) continue;
            // bind the parity buffer statically (j is a literal here)
            float4 (&ar)[2][2] = (j & 1) ? arB : arA;
            uint32_t bhB = (uint32_t)__cvta_generic_to_shared(&Bhs[sbase + j][0]);
            uint32_t blB = (uint32_t)__cvta_generic_to_shared(&Bls[sbase + j][0]);

            // --- kk=0 B fragments issued FIRST: split2 below covers LDS latency
            uint32_t bhf0[4][2], blf0[4][2];
#pragma unroll
            for (int ntp = 0; ntp < 2; ntp++) {
                int rrow = (lane & 15);
                int rcol = ntp * 16 + (lane >> 4) * 8;
                uint32_t off = (uint32_t)(rrow * BPITCH + rcol) * 2;
                uint32_t t[4];
                LDSM4T(t, bhB + off);
                bhf0[ntp * 2][0] = t[0]; bhf0[ntp * 2][1] = t[1];
                bhf0[ntp * 2 + 1][0] = t[2]; bhf0[ntp * 2 + 1][1] = t[3];
                LDSM4T(t, blB + off);
                blf0[ntp * 2][0] = t[0]; blf0[ntp * 2][1] = t[1];
                blf0[ntp * 2 + 1][0] = t[2]; blf0[ntp * 2 + 1][1] = t[3];
            }

            // A fragments: float4 halves are a01/a45 directly (k-permuted B)
            uint32_t ahf[2][4], alf[2][4];
#pragma unroll
            for (int kk = 0; kk < 2; kk++) {
                split2(ar[0][kk].x, ar[0][kk].y, ahf[kk][0], alf[kk][0]);
                split2(ar[1][kk].x, ar[1][kk].y, ahf[kk][1], alf[kk][1]);
                split2(ar[0][kk].z, ar[0][kk].w, ahf[kk][2], alf[kk][2]);
                split2(ar[1][kk].z, ar[1][kk].w, ahf[kk][3], alf[kk][3]);
            }
            // prefetch A chunk c+2 into the SAME parity buffer (2-deep)
            if (c + 2 < c1) LOADA(ar, c + 2);

            // kk=0 MMAs (term-major: 4 independent between accumulator reuse)
#pragma unroll
            for (int nt = 0; nt < 4; nt++) MMABF16(d[nt], ahf[0], bhf0[nt]);
#pragma unroll
            for (int nt = 0; nt < 4; nt++) MMABF16(d[nt], ahf[0], blf0[nt]);
#pragma unroll
            for (int nt = 0; nt < 4; nt++) MMABF16(d[nt], alf[0], bhf0[nt]);

            // kk=1 B fragments + MMAs
            {
                uint32_t bhf[4][2], blf[4][2];
#pragma unroll
                for (int ntp = 0; ntp < 2; ntp++) {
                    int rrow = 16 + (lane & 15);
                    int rcol = ntp * 16 + (lane >> 4) * 8;
                    uint32_t off = (uint32_t)(rrow * BPITCH + rcol) * 2;
                    uint32_t t[4];
                    LDSM4T(t, bhB + off);
                    bhf[ntp * 2][0] = t[0]; bhf[ntp * 2][1] = t[1];
                    bhf[ntp * 2 + 1][0] = t[2]; bhf[ntp * 2 + 1][1] = t[3];
                    LDSM4T(t, blB + off);
                    blf[ntp * 2][0] = t[0]; blf[ntp * 2][1] = t[1];
                    blf[ntp * 2 + 1][0] = t[2]; blf[ntp * 2 + 1][1] = t[3];
                }
#pragma unroll
                for (int nt = 0; nt < 4; nt++) MMABF16(d[nt], ahf[1], bhf[nt]);
#pragma unroll
                for (int nt = 0; nt < 4; nt++) MMABF16(d[nt], ahf[1], blf[nt]);
#pragma unroll
                for (int nt = 0; nt < 4; nt++) MMABF16(d[nt], alf[1], bhf[nt]);
            }
        }
    }
#undef LOADA

    float* slab = g_Pf + (size_t)blockIdx.y * Mrows * 32;
#pragma unroll
    for (int nt = 0; nt < 4; nt++) {
        int n = nt * 8 + t4 * 2;
        *(float2*)(slab + (size_t)row0 * 32 + n)       = make_float2(d[nt][0], d[nt][1]);
        *(float2*)(slab + (size_t)(row0 + 8) * 32 + n) = make_float2(d[nt][2], d[nt][3]);
    }
}

// ---------------- fold K-split partials -> coeff, s[b] = sum coeff^2 ------
__global__ void k_reduce(int phase) {
    __shared__ float sAcc[32];
    int tid = threadIdx.x;
    if (tid < 32) sAcc[tid] = 0.f;
    __syncthreads();
    int Ksp   = phase ? KS2 : KS1;
    int Mrows = phase ? MR2 : MR1;
    int M     = phase ? N12c : N1c;
    float* coeff = phase ? g_cz : g_cy;
    float* sOut  = phase ? g_sz : g_sy;
    int u = blockIdx.x * 256 + tid;
    int b = u & 31;
    if (u < M * 32) {
        float s = 0.f;
        for (int j = 0; j < Ksp; j++) s += g_Pf[(size_t)j * Mrows * 32 + u];
        coeff[u] = s;
        atomicAdd(&sAcc[b], s * s);
    }
    __syncthreads();
    if (tid < 32) atomicAdd(&sOut[tid], sAcc[tid]);
}

// ------------- final outputs (y & z corrections applied on the fly) -------
__global__ void k_out(float* __restrict__ out) {
    int u = blockIdx.x * 256 + threadIdx.x;
    if (u >= N12c * Bz) return;
    int v = u >> 5, b = u & 31;
    float corr = g_cz[u] * (g_a[b] / g_sz[b]);
    float X = g_px[u], Z = g_pz[u] + corr;
    if (v < N1c) {
        float Yv = g_py[u] + g_cy[u] * (g_a[b] / g_sy[b]);
        float* o = out + (size_t)b * (N1c * 3) + v * 3;
        o[0] = X; o[1] = Yv; o[2] = Z;
    } else {
        int j = v - N1c;
        float* o = out + (size_t)Bz * N1c * 3 + (size_t)b * (N2c * 2) + j * 2;
        o[0] = X; o[1] = Z;
    }
}

extern "C" void kernel_launch(void* const* d_in, const int* in_sizes, int n_in,
                              void* d_out, int out_size) {
    const float* x   = (const float*)d_in[0];
    const float* y   = (const float*)d_in[1];
    const float* p0  = (const float*)d_in[2];
    const int*   tri = (const int*)d_in[3];
    const float* Vx  = (const float*)d_in[6];
    const float* Vxy = (const float*)d_in[7];
    float* out = (float*)d_out;
    (void)in_sizes; (void)n_in; (void)out_size;

    k_init<<<1500, 256>>>(x, y, p0);
    k_det<<<1250, 256>>>(tri, p0, 0);
    k_a<<<1, 256>>>();
    k_gemm_tc<<<dim3(MT1, KS1), 256>>>(Vx, N1c, MR1, CPS1);
    k_reduce<<<500, 256>>>(0);
    k_det<<<1250, 256>>>(tri, p0, 1);
    k_gemm_tc<<<dim3(MT2, KS2), 256>>>(Vxy, N12c, MR2, CPS2);
    k_reduce<<<625, 256>>>(1);
    k_out<<<625, 256>>>(out);
}

// round 13
// speedup vs baseline: 1.0010x; 1.0010x over previous
#include <cuda_runtime.h>
#include <cuda_bf16.h>
#include <cstdint>

#define Bz   32
#define NV   12000
#define NT   20000
#define N1c  4000
#define N2c  1000
#define N12c 5000
#define KKc  20000
#define KC   625            // 32-wide k-chunks (625*32 = 20000 exactly)

// GEMM1: 32 m-tiles (4096 rows), Ksplit 9 (70 chunks/split, last 65)
#define MT1 32
#define MR1 4096
#define KS1 9
#define CPS1 70
// GEMM2: 40 m-tiles (5120 rows), Ksplit 7 (90 chunks/split, last 85)
#define MT2 40
#define MR2 5120
#define KS2 7
#define CPS2 90

#define BPITCH 40   // bf16 elems per B smem row (80B, conflict-free ldmatrix)

// ---------------- device scratch (static; no allocations) ----------------
__device__ float  g_px[NV * Bz];            // [v*32 + b]
__device__ float  g_py[NV * Bz];
__device__ float  g_pz[NV * Bz];
__device__ __nv_bfloat16 g_Bh[NT * Bz];     // B hi split, rows k-permuted per 16
__device__ __nv_bfloat16 g_Bl[NT * Bz];     // B lo split
__device__ float  g_cy[N1c * Bz];           // coeffy [i*32 + b]
__device__ float  g_cz[N12c * Bz];
__device__ float  g_Pf[(size_t)KS1 * MR1 * 32];  // K-split partial slab
__device__ float2 g_volP[1250 * 16];
__device__ float  g_volcP[1250];
__device__ float  g_a[Bz];
__device__ float  g_sy[Bz];
__device__ float  g_sz[Bz];

// k-permutation within each 16-group: physical pair q -> logical pair
// (q even ? q/2 : 4 + q/2). Makes A float4 halves = MMA a01/a45 directly.
__device__ __forceinline__ int kperm(int p) {
    int q = p >> 1;
    int lp = (q & 1) ? 4 + (q >> 1) : (q >> 1);
    return lp * 2 + (p & 1);
}

// ---------------- K0: build SoA points (batch-fastest) + zero sums --------
__global__ void k_init(const float* __restrict__ x, const float* __restrict__ y,
                       const float* __restrict__ p0) {
    int u = blockIdx.x * 256 + threadIdx.x;
    if (u < 64) { if (u < 32) g_sy[u] = 0.f; else g_sz[u - 32] = 0.f; }
    if (u >= NV * Bz) return;
    int v = u >> 5, b = u & 31;
    float px, py, pz;
    if (v < N1c) {
        const float* xb = x + (size_t)b * (N1c * 3) + v * 3;
        px = xb[0]; py = xb[1]; pz = xb[2];
    } else if (v < N12c) {
        int j = v - N1c;
        const float* yb = y + (size_t)b * (N2c * 2) + j * 2;
        px = yb[0]; pz = yb[1]; py = p0[v * 3 + 1];
    } else {
        px = p0[v * 3]; py = p0[v * 3 + 1]; pz = p0[v * 3 + 2];
    }
    g_px[u] = px; g_py[u] = py; g_pz[u] = pz;
}

// helper: split a pair of floats into bf16 hi/lo packed words
__device__ __forceinline__ void split2(float f0, float f1, uint32_t& hw, uint32_t& lw) {
    __nv_bfloat162 h = __floats2bfloat162_rn(f0, f1);
    float r0 = f0 - __bfloat162float(h.x);
    float r1 = f1 - __bfloat162float(h.y);
    __nv_bfloat162 l = __floats2bfloat162_rn(r0, r1);
    hw = *(uint32_t*)&h; lw = *(uint32_t*)&l;
}

// ---------------- K1: per-triangle dets -> bf16-split B (permuted rows) ---
// phase 1 reads py WITH the rank-1 y-correction applied on the fly
__global__ void k_det(const int* __restrict__ tri, const float* __restrict__ p0,
                      int phase) {
    __shared__ float2 sv[16];
    __shared__ float  sc;
    int tid = threadIdx.x;
    if (phase == 0) {
        if (tid < 16) sv[tid] = make_float2(0.f, 0.f);
        if (tid == 0) sc = 0.f;
        __syncthreads();
    }
    int u = blockIdx.x * 256 + tid;
    int t = u >> 4, b2 = u & 15;
    if (t < NT) {
        int v0 = tri[t * 3], v1 = tri[t * 3 + 1], v2 = tri[t * 3 + 2];
        const float2* PX = (const float2*)g_px;
        const float2* PY = (const float2*)g_py;
        const float2* PZ = (const float2*)g_pz;
        float2 x0 = PX[v0 * 16 + b2], x1 = PX[v1 * 16 + b2], x2 = PX[v2 * 16 + b2];
        float2 d;
        if (phase == 0) {
            float2 z0 = PZ[v0 * 16 + b2], z1 = PZ[v1 * 16 + b2], z2 = PZ[v2 * 16 + b2];
            float2 y0 = PY[v0 * 16 + b2], y1 = PY[v1 * 16 + b2], y2 = PY[v2 * 16 + b2];
            d.x = ((x0.x - x1.x) * (z2.x - z1.x) - (z0.x - z1.x) * (x2.x - x1.x)) * (1.f / 6.f);
            d.y = ((x0.y - x1.y) * (z2.y - z1.y) - (z0.y - z1.y) * (x2.y - x1.y)) * (1.f / 6.f);
            atomicAdd(&sv[b2].x, (y0.x + y1.x + y2.x) * d.x);
            atomicAdd(&sv[b2].y, (y0.y + y1.y + y2.y) * d.y);
            if (b2 == 0) {
                float X0 = p0[v0 * 3], Y0 = p0[v0 * 3 + 1], Z0 = p0[v0 * 3 + 2];
                float X1 = p0[v1 * 3], Y1 = p0[v1 * 3 + 1], Z1 = p0[v1 * 3 + 2];
                float X2 = p0[v2 * 3], Y2 = p0[v2 * 3 + 1], Z2 = p0[v2 * 3 + 2];
                float d0 = ((X0 - X1) * (Z2 - Z1) - (Z0 - Z1) * (X2 - X1)) * (1.f / 6.f);
                atomicAdd(&sc, (Y0 + Y1 + Y2) * d0);
            }
        } else {
            float2 av = ((const float2*)g_a)[b2];
            float2 sy = ((const float2*)g_sy)[b2];
            float2 rat = make_float2(av.x / sy.x, av.y / sy.y);
            float2 y0 = PY[v0 * 16 + b2], y1 = PY[v1 * 16 + b2], y2 = PY[v2 * 16 + b2];
            if (v0 < N1c) { float2 c = *(const float2*)(g_cy + v0 * 32 + 2 * b2);
                            y0.x += c.x * rat.x; y0.y += c.y * rat.y; }
            if (v1 < N1c) { float2 c = *(const float2*)(g_cy + v1 * 32 + 2 * b2);
                            y1.x += c.x * rat.x; y1.y += c.y * rat.y; }
            if (v2 < N1c) { float2 c = *(const float2*)(g_cy + v2 * 32 + 2 * b2);
                            y2.x += c.x * rat.x; y2.y += c.y * rat.y; }
            d.x = ((x0.x - x2.x) * (y1.x - y2.x) - (y0.x - y2.x) * (x1.x - x2.x)) * (1.f / 6.f);
            d.y = ((x0.y - x2.y) * (y1.y - y2.y) - (y0.y - y2.y) * (x1.y - x2.y)) * (1.f / 6.f);
        }
        uint32_t hw, lw;
        split2(d.x, d.y, hw, lw);
        int tp = (t & ~15) | kperm(t & 15);   // permuted row for GEMM
        *(uint32_t*)(g_Bh + tp * 32 + 2 * b2) = hw;
        *(uint32_t*)(g_Bl + tp * 32 + 2 * b2) = lw;
    }
    if (phase == 0) {
        __syncthreads();
        if (tid < 16) g_volP[blockIdx.x * 16 + tid] = sv[tid];
        if (tid == 0) g_volcP[blockIdx.x] = sc;
    }
}

// ---------------- K2: reduce volume partials -> a[b] ----------------------
__global__ void k_a() {
    __shared__ float2 red[256];
    __shared__ float  redc[256];
    int tid = threadIdx.x;
    int b2 = tid & 15, r = tid >> 4;
    float2 s = make_float2(0.f, 0.f);
    for (int j = r; j < 1250; j += 16) {
        float2 v = g_volP[j * 16 + b2]; s.x += v.x; s.y += v.y;
    }
    red[tid] = s;
    float c = 0.f;
    for (int j = tid; j < 1250; j += 256) c += g_volcP[j];
    redc[tid] = c;
    __syncthreads();
    for (int h = 8; h > 0; h >>= 1) {
        if (r < h) { red[tid].x += red[tid + h * 16].x; red[tid].y += red[tid + h * 16].y; }
        __syncthreads();
    }
    for (int h = 128; h > 0; h >>= 1) {
        if (tid < h) redc[tid] += redc[tid + h];
        __syncthreads();
    }
    if (tid < 32) {
        float volc = redc[0];
        float2 vb = red[tid >> 1];
        float volb = (tid & 1) ? vb.y : vb.x;
        g_a[tid] = 0.5f * (volc - volb);
    }
}

// ------- tensor-core GEMM: A LDG.128 2-deep, B 8-slab single-sync ring ----
#define LDSM4T(r, addr) \
    asm volatile("ldmatrix.sync.aligned.m8n8.x4.trans.shared.b16 {%0,%1,%2,%3}, [%4];" \
        : "=r"((r)[0]), "=r"((r)[1]), "=r"((r)[2]), "=r"((r)[3]) : "r"(addr))
#define MMABF16(dd, aa, bb) \
    asm volatile("mma.sync.aligned.m16n8k16.row.col.f32.bf16.bf16.f32 " \
        "{%0,%1,%2,%3}, {%4,%5,%6,%7}, {%8,%9}, {%0,%1,%2,%3};" \
        : "+f"((dd)[0]), "+f"((dd)[1]), "+f"((dd)[2]), "+f"((dd)[3]) \
        : "r"((aa)[0]), "r"((aa)[1]), "r"((aa)[2]), "r"((aa)[3]), \
          "r"((bb)[0]), "r"((bb)[1]))

__global__ void __launch_bounds__(256, 2)
k_gemm_tc(const float* __restrict__ A, int M, int Mrows, int cps) {
    __shared__ __align__(16) __nv_bfloat16 Bhs[8][32 * BPITCH];
    __shared__ __align__(16) __nv_bfloat16 Bls[8][32 * BPITCH];

    int tid = threadIdx.x;
    int lane = tid & 31, w = tid >> 5;      // 8 warps, each owns m16 rows
    int g = lane >> 2, t4 = lane & 3;
    int ibase = blockIdx.x * 128;
    int c0 = blockIdx.y * cps;
    int c1 = min(KC, c0 + cps);

    int row0 = ibase + w * 16 + g;
    bool v0 = row0 < M, v8 = (row0 + 8) < M;
    const float* A0 = A + (size_t)row0 * KKc + t4 * 4;
    const float* A8 = A0 + (size_t)8 * KKc;

    int bk = tid >> 3, bn = (tid & 7) * 4;  // B staging: 32 rows x 32 cols
    const size_t bOff = (size_t)bk * 32 + bn;

    // Two A chunk buffers, parity-static (selected by compile-time j&1).
    float4 arA[2][2], arB[2][2];            // [row r][kk]
    uint2 bhr[4], blr[4];
    const float4 z4 = make_float4(0.f, 0.f, 0.f, 0.f);

#define LOADA(buf, c) do { \
        int _kb = (c) * 32; \
        buf[0][0] = v0 ? *(const float4*)(A0 + _kb)      : z4; \
        buf[0][1] = v0 ? *(const float4*)(A0 + _kb + 16) : z4; \
        buf[1][0] = v8 ? *(const float4*)(A8 + _kb)      : z4; \
        buf[1][1] = v8 ? *(const float4*)(A8 + _kb + 16) : z4; \
    } while (0)

    // prefetch A chunks c0 (parity 0) and c0+1 (parity 1)
    LOADA(arA, c0);
    if (c0 + 1 < c1) LOADA(arB, c0 + 1);
    // prefetch B group [c0, c0+4)
#pragma unroll
    for (int j = 0; j < 4; j++) {
        int c = c0 + j;
        if (c < c1) {
            bhr[j] = *(const uint2*)(g_Bh + (size_t)c * 1024 + bOff);
            blr[j] = *(const uint2*)(g_Bl + (size_t)c * 1024 + bOff);
        }
    }

    float d[4][4];
#pragma unroll
    for (int nt = 0; nt < 4; nt++)
#pragma unroll
        for (int q = 0; q < 4; q++) d[nt][q] = 0.f;

    int gi = 0;
    for (int cb = c0; cb < c1; cb += 4, gi ^= 1) {
        int sbase = gi * 4;                 // alternating 4-slab half
        // stage this group's B (registers -> smem), single barrier
#pragma unroll
        for (int j = 0; j < 4; j++)
            if (cb + j < c1) {
                *(uint2*)(&Bhs[sbase + j][bk * BPITCH + bn]) = bhr[j];
                *(uint2*)(&Bls[sbase + j][bk * BPITCH + bn]) = blr[j];
            }
        __syncthreads();
        // prefetch next B group (flies during ~4 chunks of compute)
#pragma unroll
        for (int j = 0; j < 4; j++) {
            int c = cb + 4 + j;
            if (c < c1) {
                bhr[j] = *(const uint2*)(g_Bh + (size_t)c * 1024 + bOff);
                blr[j] = *(const uint2*)(g_Bl + (size_t)c * 1024 + bOff);
            }
        }
#pragma unroll
        for (int j = 0; j < 4; j++) {
            int c = cb + j;
            if (c >= c1) continue;
            // bind the parity buffer statically (j is a literal here)
            float4 (&ar)[2][2] = (j & 1) ? arB : arA;
            uint32_t bhB = (uint32_t)__cvta_generic_to_shared(&Bhs[sbase + j][0]);
            uint32_t blB = (uint32_t)__cvta_generic_to_shared(&Bls[sbase + j][0]);

            // --- kk=0 B fragments issued FIRST: split2 below covers LDS latency
            uint32_t bhf0[4][2], blf0[4][2];
#pragma unroll
            for (int ntp = 0; ntp < 2; ntp++) {
                int rrow = (lane & 15);
                int rcol = ntp * 16 + (lane >> 4) * 8;
                uint32_t off = (uint32_t)(rrow * BPITCH + rcol) * 2;
                uint32_t t[4];
                LDSM4T(t, bhB + off);
                bhf0[ntp * 2][0] = t[0]; bhf0[ntp * 2][1] = t[1];
                bhf0[ntp * 2 + 1][0] = t[2]; bhf0[ntp * 2 + 1][1] = t[3];
                LDSM4T(t, blB + off);
                blf0[ntp * 2][0] = t[0]; blf0[ntp * 2][1] = t[1];
                blf0[ntp * 2 + 1][0] = t[2]; blf0[ntp * 2 + 1][1] = t[3];
            }

            // A fragments: float4 halves are a01/a45 directly (k-permuted B)
            uint32_t ahf[2][4], alf[2][4];
#pragma unroll
            for (int kk = 0; kk < 2; kk++) {
                split2(ar[0][kk].x, ar[0][kk].y, ahf[kk][0], alf[kk][0]);
                split2(ar[1][kk].x, ar[1][kk].y, ahf[kk][1], alf[kk][1]);
                split2(ar[0][kk].z, ar[0][kk].w, ahf[kk][2], alf[kk][2]);
                split2(ar[1][kk].z, ar[1][kk].w, ahf[kk][3], alf[kk][3]);
            }
            // prefetch A chunk c+2 into the SAME parity buffer (2-deep)
            if (c + 2 < c1) LOADA(ar, c + 2);

            // kk=0 MMAs (term-major: 4 independent between accumulator reuse)
#pragma unroll
            for (int nt = 0; nt < 4; nt++) MMABF16(d[nt], ahf[0], bhf0[nt]);
#pragma unroll
            for (int nt = 0; nt < 4; nt++) MMABF16(d[nt], ahf[0], blf0[nt]);
#pragma unroll
            for (int nt = 0; nt < 4; nt++) MMABF16(d[nt], alf[0], bhf0[nt]);

            // kk=1 B fragments + MMAs
            {
                uint32_t bhf[4][2], blf[4][2];
#pragma unroll
                for (int ntp = 0; ntp < 2; ntp++) {
                    int rrow = 16 + (lane & 15);
                    int rcol = ntp * 16 + (lane >> 4) * 8;
                    uint32_t off = (uint32_t)(rrow * BPITCH + rcol) * 2;
                    uint32_t t[4];
                    LDSM4T(t, bhB + off);
                    bhf[ntp * 2][0] = t[0]; bhf[ntp * 2][1] = t[1];
                    bhf[ntp * 2 + 1][0] = t[2]; bhf[ntp * 2 + 1][1] = t[3];
                    LDSM4T(t, blB + off);
                    blf[ntp * 2][0] = t[0]; blf[ntp * 2][1] = t[1];
                    blf[ntp * 2 + 1][0] = t[2]; blf[ntp * 2 + 1][1] = t[3];
                }
#pragma unroll
                for (int nt = 0; nt < 4; nt++) MMABF16(d[nt], ahf[1], bhf[nt]);
#pragma unroll
                for (int nt = 0; nt < 4; nt++) MMABF16(d[nt], ahf[1], blf[nt]);
#pragma unroll
                for (int nt = 0; nt < 4; nt++) MMABF16(d[nt], alf[1], bhf[nt]);
            }
        }
    }
#undef LOADA

    float* slab = g_Pf + (size_t)blockIdx.y * Mrows * 32;
#pragma unroll
    for (int nt = 0; nt < 4; nt++) {
        int n = nt * 8 + t4 * 2;
        *(float2*)(slab + (size_t)row0 * 32 + n)       = make_float2(d[nt][0], d[nt][1]);
        *(float2*)(slab + (size_t)(row0 + 8) * 32 + n) = make_float2(d[nt][2], d[nt][3]);
    }
}

// ---------------- fold K-split partials -> coeff, s[b] = sum coeff^2 ------
__global__ void k_reduce(int phase) {
    __shared__ float sAcc[32];
    int tid = threadIdx.x;
    if (tid < 32) sAcc[tid] = 0.f;
    __syncthreads();
    int Ksp   = phase ? KS2 : KS1;
    int Mrows = phase ? MR2 : MR1;
    int M     = phase ? N12c : N1c;
    float* coeff = phase ? g_cz : g_cy;
    float* sOut  = phase ? g_sz : g_sy;
    int u = blockIdx.x * 256 + tid;
    int b = u & 31;
    if (u < M * 32) {
        float s = 0.f;
        for (int j = 0; j < Ksp; j++) s += g_Pf[(size_t)j * Mrows * 32 + u];
        coeff[u] = s;
        atomicAdd(&sAcc[b], s * s);
    }
    __syncthreads();
    if (tid < 32) atomicAdd(&sOut[tid], sAcc[tid]);
}

// ------------- final outputs (y & z corrections applied on the fly) -------
__global__ void k_out(float* __restrict__ out) {
    int u = blockIdx.x * 256 + threadIdx.x;
    if (u >= N12c * Bz) return;
    int v = u >> 5, b = u & 31;
    float corr = g_cz[u] * (g_a[b] / g_sz[b]);
    float X = g_px[u], Z = g_pz[u] + corr;
    if (v < N1c) {
        float Yv = g_py[u] + g_cy[u] * (g_a[b] / g_sy[b]);
        float* o = out + (size_t)b * (N1c * 3) + v * 3;
        o[0] = X; o[1] = Yv; o[2] = Z;
    } else {
        int j = v - N1c;
        float* o = out + (size_t)Bz * N1c * 3 + (size_t)b * (N2c * 2) + j * 2;
        o[0] = X; o[1] = Z;
    }
}

extern "C" void kernel_launch(void* const* d_in, const int* in_sizes, int n_in,
                              void* d_out, int out_size) {
    const float* x   = (const float*)d_in[0];
    const float* y   = (const float*)d_in[1];
    const float* p0  = (const float*)d_in[2];
    const int*   tri = (const int*)d_in[3];
    const float* Vx  = (const float*)d_in[6];
    const float* Vxy = (const float*)d_in[7];
    float* out = (float*)d_out;
    (void)in_sizes; (void)n_in; (void)out_size;

    k_init<<<1500, 256>>>(x, y, p0);
    k_det<<<1250, 256>>>(tri, p0, 0);
    k_a<<<1, 256>>>();
    k_gemm_tc<<<dim3(MT1, KS1), 256>>>(Vx, N1c, MR1, CPS1);
    k_reduce<<<500, 256>>>(0);
    k_det<<<1250, 256>>>(tri, p0, 1);
    k_gemm_tc<<<dim3(MT2, KS2), 256>>>(Vxy, N12c, MR2, CPS2);
    k_reduce<<<625, 256>>>(1);
    k_out<<<625, 256>>>(out);
}

// round 14
// speedup vs baseline: 1.0786x; 1.0775x over previous
#include <cuda_runtime.h>
#include <cuda_fp16.h>
#include <cstdint>

#define Bz   32
#define NV   12000
#define NT   20000
#define N1c  4000
#define N2c  1000
#define N12c 5000
#define KKc  20000
#define KC   625            // 32-wide k-chunks (625*32 = 20000 exactly)

// GEMM1: 32 m-tiles (4096 rows), Ksplit 9 (70 chunks/split, last 65)
#define MT1 32
#define MR1 4096
#define KS1 9
#define CPS1 70
// GEMM2: 40 m-tiles (5120 rows), Ksplit 7 (90 chunks/split, last 85)
#define MT2 40
#define MR2 5120
#define KS2 7
#define CPS2 90

#define BPITCH 40   // fp16 elems per B smem row (80B, conflict-free ldmatrix)

// ---------------- device scratch (static; no allocations) ----------------
__device__ float  g_px[NV * Bz];            // [v*32 + b]
__device__ float  g_py[NV * Bz];
__device__ float  g_pz[NV * Bz];
__device__ __half g_Bh[NT * Bz];            // B hi split, rows k-permuted per 16
__device__ __half g_Bl[NT * Bz];            // B lo split
__device__ float  g_cy[N1c * Bz];           // coeffy [i*32 + b]
__device__ float  g_cz[N12c * Bz];
__device__ float  g_Pf[(size_t)KS1 * MR1 * 32];  // K-split partial slab
__device__ float  g_vol[Bz];                // per-batch volume (atomic)
__device__ float  g_volc[1];                // base-mesh volume (atomic)
__device__ float  g_sy[Bz];
__device__ float  g_sz[Bz];

// k-permutation within each 16-group: physical pair q -> logical pair
// (q even ? q/2 : 4 + q/2). Makes A float4 halves = MMA a01/a45 directly.
__device__ __forceinline__ int kperm(int p) {
    int q = p >> 1;
    int lp = (q & 1) ? 4 + (q >> 1) : (q >> 1);
    return lp * 2 + (p & 1);
}

__device__ __forceinline__ uint32_t packh2(float a, float b) {
    __half2 h = __floats2half2_rn(a, b);
    return *(uint32_t*)&h;
}

// ---------------- K0: build SoA points (batch-fastest) + zero sums --------
__global__ void k_init(const float* __restrict__ x, const float* __restrict__ y,
                       const float* __restrict__ p0) {
    int u = blockIdx.x * 256 + threadIdx.x;
    if (u < 128) {
        if (u < 32) g_sy[u] = 0.f;
        else if (u < 64) g_sz[u - 32] = 0.f;
        else if (u < 96) g_vol[u - 64] = 0.f;
        else if (u == 96) g_volc[0] = 0.f;
    }
    if (u >= NV * Bz) return;
    int v = u >> 5, b = u & 31;
    float px, py, pz;
    if (v < N1c) {
        const float* xb = x + (size_t)b * (N1c * 3) + v * 3;
        px = xb[0]; py = xb[1]; pz = xb[2];
    } else if (v < N12c) {
        int j = v - N1c;
        const float* yb = y + (size_t)b * (N2c * 2) + j * 2;
        px = yb[0]; pz = yb[1]; py = p0[v * 3 + 1];
    } else {
        px = p0[v * 3]; py = p0[v * 3 + 1]; pz = p0[v * 3 + 2];
    }
    g_px[u] = px; g_py[u] = py; g_pz[u] = pz;
}

// ---------------- K1: per-triangle dets -> fp16-split B (permuted rows) ---
// phase 1 reads py WITH the rank-1 y-correction applied on the fly
__global__ void k_det(const int* __restrict__ tri, const float* __restrict__ p0,
                      int phase) {
    __shared__ float2 sv[16];
    __shared__ float  sc;
    int tid = threadIdx.x;
    if (phase == 0) {
        if (tid < 16) sv[tid] = make_float2(0.f, 0.f);
        if (tid == 0) sc = 0.f;
        __syncthreads();
    }
    int u = blockIdx.x * 256 + tid;
    int t = u >> 4, b2 = u & 15;
    if (t < NT) {
        int v0 = tri[t * 3], v1 = tri[t * 3 + 1], v2 = tri[t * 3 + 2];
        const float2* PX = (const float2*)g_px;
        const float2* PY = (const float2*)g_py;
        const float2* PZ = (const float2*)g_pz;
        float2 x0 = PX[v0 * 16 + b2], x1 = PX[v1 * 16 + b2], x2 = PX[v2 * 16 + b2];
        float2 d;
        if (phase == 0) {
            float2 z0 = PZ[v0 * 16 + b2], z1 = PZ[v1 * 16 + b2], z2 = PZ[v2 * 16 + b2];
            float2 y0 = PY[v0 * 16 + b2], y1 = PY[v1 * 16 + b2], y2 = PY[v2 * 16 + b2];
            d.x = ((x0.x - x1.x) * (z2.x - z1.x) - (z0.x - z1.x) * (x2.x - x1.x)) * (1.f / 6.f);
            d.y = ((x0.y - x1.y) * (z2.y - z1.y) - (z0.y - z1.y) * (x2.y - x1.y)) * (1.f / 6.f);
            atomicAdd(&sv[b2].x, (y0.x + y1.x + y2.x) * d.x);
            atomicAdd(&sv[b2].y, (y0.y + y1.y + y2.y) * d.y);
            if (b2 == 0) {
                float X0 = p0[v0 * 3], Y0 = p0[v0 * 3 + 1], Z0 = p0[v0 * 3 + 2];
                float X1 = p0[v1 * 3], Y1 = p0[v1 * 3 + 1], Z1 = p0[v1 * 3 + 2];
                float X2 = p0[v2 * 3], Y2 = p0[v2 * 3 + 1], Z2 = p0[v2 * 3 + 2];
                float d0 = ((X0 - X1) * (Z2 - Z1) - (Z0 - Z1) * (X2 - X1)) * (1.f / 6.f);
                atomicAdd(&sc, (Y0 + Y1 + Y2) * d0);
            }
        } else {
            float2 vv = ((const float2*)g_vol)[b2];
            float  vc = g_volc[0];
            float2 sy = ((const float2*)g_sy)[b2];
            float2 rat = make_float2(0.5f * (vc - vv.x) / sy.x,
                                     0.5f * (vc - vv.y) / sy.y);
            float2 y0 = PY[v0 * 16 + b2], y1 = PY[v1 * 16 + b2], y2 = PY[v2 * 16 + b2];
            if (v0 < N1c) { float2 c = *(const float2*)(g_cy + v0 * 32 + 2 * b2);
                            y0.x += c.x * rat.x; y0.y += c.y * rat.y; }
            if (v1 < N1c) { float2 c = *(const float2*)(g_cy + v1 * 32 + 2 * b2);
                            y1.x += c.x * rat.x; y1.y += c.y * rat.y; }
            if (v2 < N1c) { float2 c = *(const float2*)(g_cy + v2 * 32 + 2 * b2);
                            y2.x += c.x * rat.x; y2.y += c.y * rat.y; }
            d.x = ((x0.x - x2.x) * (y1.x - y2.x) - (y0.x - y2.x) * (x1.x - x2.x)) * (1.f / 6.f);
            d.y = ((x0.y - x2.y) * (y1.y - y2.y) - (y0.y - y2.y) * (x1.y - x2.y)) * (1.f / 6.f);
        }
        // fp16 hi/lo split
        __half2 h = __floats2half2_rn(d.x, d.y);
        float r0 = d.x - __half2float(h.x);
        float r1 = d.y - __half2float(h.y);
        __half2 l = __floats2half2_rn(r0, r1);
        int tp = (t & ~15) | kperm(t & 15);   // permuted row for GEMM
        *(uint32_t*)(g_Bh + tp * 32 + 2 * b2) = *(uint32_t*)&h;
        *(uint32_t*)(g_Bl + tp * 32 + 2 * b2) = *(uint32_t*)&l;
    }
    if (phase == 0) {
        __syncthreads();
        if (tid < 16) {
            atomicAdd(&g_vol[2 * tid],     sv[tid].x);
            atomicAdd(&g_vol[2 * tid + 1], sv[tid].y);
        }
        if (tid == 0) atomicAdd(&g_volc[0], sc);
    }
}

// ------- tensor-core GEMM: A fp16 single-term, B fp16 hi/lo via smem ------
#define LDSM4T(r, addr) \
    asm volatile("ldmatrix.sync.aligned.m8n8.x4.trans.shared.b16 {%0,%1,%2,%3}, [%4];" \
        : "=r"((r)[0]), "=r"((r)[1]), "=r"((r)[2]), "=r"((r)[3]) : "r"(addr))
#define MMAF16(dd, aa, bb) \
    asm volatile("mma.sync.aligned.m16n8k16.row.col.f32.f16.f16.f32 " \
        "{%0,%1,%2,%3}, {%4,%5,%6,%7}, {%8,%9}, {%0,%1,%2,%3};" \
        : "+f"((dd)[0]), "+f"((dd)[1]), "+f"((dd)[2]), "+f"((dd)[3]) \
        : "r"((aa)[0]), "r"((aa)[1]), "r"((aa)[2]), "r"((aa)[3]), \
          "r"((bb)[0]), "r"((bb)[1]))

__global__ void __launch_bounds__(256, 2)
k_gemm_tc(const float* __restrict__ A, int M, int Mrows, int cps) {
    __shared__ __align__(16) __half Bhs[4][32 * BPITCH];
    __shared__ __align__(16) __half Bls[4][32 * BPITCH];

    int tid = threadIdx.x;
    int lane = tid & 31, w = tid >> 5;      // 8 warps, each owns m16 rows
    int g = lane >> 2, t4 = lane & 3;
    int ibase = blockIdx.x * 128;
    int c0 = blockIdx.y * cps;
    int c1 = min(KC, c0 + cps);

    int row0 = ibase + w * 16 + g;
    bool v0 = row0 < M, v8 = (row0 + 8) < M;
    const float* A0 = A + (size_t)row0 * KKc + t4 * 4;
    const float* A8 = A0 + (size_t)8 * KKc;

    int bk = tid >> 3, bn = (tid & 7) * 4;  // B staging: 32 rows x 32 cols
    const size_t bOff = (size_t)bk * 32 + bn;

    // Two A chunk buffers, parity-static (selected by compile-time j&1).
    float4 arA[2][2], arB[2][2];            // [row r][kk]
    uint2 bhr[4], blr[4];
    const float4 z4 = make_float4(0.f, 0.f, 0.f, 0.f);

#define LOADA(buf, c) do { \
        int _kb = (c) * 32; \
        buf[0][0] = v0 ? *(const float4*)(A0 + _kb)      : z4; \
        buf[0][1] = v0 ? *(const float4*)(A0 + _kb + 16) : z4; \
        buf[1][0] = v8 ? *(const float4*)(A8 + _kb)      : z4; \
        buf[1][1] = v8 ? *(const float4*)(A8 + _kb + 16) : z4; \
    } while (0)

    // prefetch A chunks c0 (parity 0) and c0+1 (parity 1)
    LOADA(arA, c0);
    if (c0 + 1 < c1) LOADA(arB, c0 + 1);
    // prefetch B group [c0, c0+4)
#pragma unroll
    for (int j = 0; j < 4; j++) {
        int c = c0 + j;
        if (c < c1) {
            bhr[j] = *(const uint2*)(g_Bh + (size_t)c * 1024 + bOff);
            blr[j] = *(const uint2*)(g_Bl + (size_t)c * 1024 + bOff);
        }
    }

    float d[4][4];
#pragma unroll
    for (int nt = 0; nt < 4; nt++)
#pragma unroll
        for (int q = 0; q < 4; q++) d[nt][q] = 0.f;

    for (int cb = c0; cb < c1; cb += 4) {
        __syncthreads();
#pragma unroll
        for (int j = 0; j < 4; j++)
            if (cb + j < c1) {
                *(uint2*)(&Bhs[j][bk * BPITCH + bn]) = bhr[j];
                *(uint2*)(&Bls[j][bk * BPITCH + bn]) = blr[j];
            }
        __syncthreads();
        // prefetch next B group (flies during compute of this group)
#pragma unroll
        for (int j = 0; j < 4; j++) {
            int c = cb + 4 + j;
            if (c < c1) {
                bhr[j] = *(const uint2*)(g_Bh + (size_t)c * 1024 + bOff);
                blr[j] = *(const uint2*)(g_Bl + (size_t)c * 1024 + bOff);
            }
        }
#pragma unroll
        for (int j = 0; j < 4; j++) {
            int c = cb + j;
            if (c >= c1) continue;
            // bind the parity buffer statically (j is a literal here)
            float4 (&ar)[2][2] = (j & 1) ? arB : arA;
            // A fragments: fp16 single-term (pack pairs; float4 halves = a01/a45)
            uint32_t ahf[2][4];
#pragma unroll
            for (int kk = 0; kk < 2; kk++) {
                ahf[kk][0] = packh2(ar[0][kk].x, ar[0][kk].y);
                ahf[kk][1] = packh2(ar[1][kk].x, ar[1][kk].y);
                ahf[kk][2] = packh2(ar[0][kk].z, ar[0][kk].w);
                ahf[kk][3] = packh2(ar[1][kk].z, ar[1][kk].w);
            }
            // prefetch A chunk c+2 into the SAME parity buffer (2-deep)
            if (c + 2 < c1) LOADA(ar, c + 2);

            // B fragments via ldmatrix.x4.trans from slab j, scoped per kk
            uint32_t bhB = (uint32_t)__cvta_generic_to_shared(&Bhs[j][0]);
            uint32_t blB = (uint32_t)__cvta_generic_to_shared(&Bls[j][0]);
#pragma unroll
            for (int kk = 0; kk < 2; kk++) {
                uint32_t bhf[4][2], blf[4][2];
#pragma unroll
                for (int ntp = 0; ntp < 2; ntp++) {
                    int rrow = kk * 16 + (lane & 15);
                    int rcol = ntp * 16 + (lane >> 4) * 8;
                    uint32_t off = (uint32_t)(rrow * BPITCH + rcol) * 2;
                    uint32_t t[4];
                    LDSM4T(t, bhB + off);
                    bhf[ntp * 2][0] = t[0]; bhf[ntp * 2][1] = t[1];
                    bhf[ntp * 2 + 1][0] = t[2]; bhf[ntp * 2 + 1][1] = t[3];
                    LDSM4T(t, blB + off);
                    blf[ntp * 2][0] = t[0]; blf[ntp * 2][1] = t[1];
                    blf[ntp * 2 + 1][0] = t[2]; blf[ntp * 2 + 1][1] = t[3];
                }
                // term-major: 4 independent MMAs between accumulator reuses
#pragma unroll
                for (int nt = 0; nt < 4; nt++) MMAF16(d[nt], ahf[kk], bhf[nt]);
#pragma unroll
                for (int nt = 0; nt < 4; nt++) MMAF16(d[nt], ahf[kk], blf[nt]);
            }
        }
    }
#undef LOADA

    float* slab = g_Pf + (size_t)blockIdx.y * Mrows * 32;
#pragma unroll
    for (int nt = 0; nt < 4; nt++) {
        int n = nt * 8 + t4 * 2;
        *(float2*)(slab + (size_t)row0 * 32 + n)       = make_float2(d[nt][0], d[nt][1]);
        *(float2*)(slab + (size_t)(row0 + 8) * 32 + n) = make_float2(d[nt][2], d[nt][3]);
    }
}

// ---------------- fold K-split partials -> coeff, s[b] = sum coeff^2 ------
__global__ void k_reduce(int phase) {
    __shared__ float sAcc[32];
    int tid = threadIdx.x;
    if (tid < 32) sAcc[tid] = 0.f;
    __syncthreads();
    int Ksp   = phase ? KS2 : KS1;
    int Mrows = phase ? MR2 : MR1;
    int M     = phase ? N12c : N1c;
    float* coeff = phase ? g_cz : g_cy;
    float* sOut  = phase ? g_sz : g_sy;
    int u = blockIdx.x * 256 + tid;
    int b = u & 31;
    if (u < M * 32) {
        float s = 0.f;
        for (int j = 0; j < Ksp; j++) s += g_Pf[(size_t)j * Mrows * 32 + u];
        coeff[u] = s;
        atomicAdd(&sAcc[b], s * s);
    }
    __syncthreads();
    if (tid < 32) atomicAdd(&sOut[tid], sAcc[tid]);
}

// ------------- final outputs (y & z corrections applied on the fly) -------
__global__ void k_out(float* __restrict__ out) {
    int u = blockIdx.x * 256 + threadIdx.x;
    if (u >= N12c * Bz) return;
    int v = u >> 5, b = u & 31;
    float a = 0.5f * (g_volc[0] - g_vol[b]);
    float corr = g_cz[u] * (a / g_sz[b]);
    float X = g_px[u], Z = g_pz[u] + corr;
    if (v < N1c) {
        float Yv = g_py[u] + g_cy[u] * (a / g_sy[b]);
        float* o = out + (size_t)b * (N1c * 3) + v * 3;
        o[0] = X; o[1] = Yv; o[2] = Z;
    } else {
        int j = v - N1c;
        float* o = out + (size_t)Bz * N1c * 3 + (size_t)b * (N2c * 2) + j * 2;
        o[0] = X; o[1] = Z;
    }
}

extern "C" void kernel_launch(void* const* d_in, const int* in_sizes, int n_in,
                              void* d_out, int out_size) {
    const float* x   = (const float*)d_in[0];
    const float* y   = (const float*)d_in[1];
    const float* p0  = (const float*)d_in[2];
    const int*   tri = (const int*)d_in[3];
    const float* Vx  = (const float*)d_in[6];
    const float* Vxy = (const float*)d_in[7];
    float* out = (float*)d_out;
    (void)in_sizes; (void)n_in; (void)out_size;

    k_init<<<1500, 256>>>(x, y, p0);
    k_det<<<1250, 256>>>(tri, p0, 0);
    k_gemm_tc<<<dim3(MT1, KS1), 256>>>(Vx, N1c, MR1, CPS1);
    k_reduce<<<500, 256>>>(0);
    k_det<<<1250, 256>>>(tri, p0, 1);
    k_gemm_tc<<<dim3(MT2, KS2), 256>>>(Vxy, N12c, MR2, CPS2);
    k_reduce<<<625, 256>>>(1);
    k_out<<<625, 256>>>(out);
}

// round 15
// speedup vs baseline: 1.1035x; 1.0231x over previous
#include <cuda_runtime.h>
#include <cuda_fp16.h>
#include <cstdint>

#define Bz   32
#define NV   12000
#define NT   20000
#define N1c  4000
#define N2c  1000
#define N12c 5000
#define KKc  20000
#define KC   625            // 32-wide k-chunks (625*32 = 20000 exactly)

// GEMM1: 32 m-tiles (4096 rows), Ksplit 9 (70 chunks/split, last 65)
#define MT1 32
#define MR1 4096
#define KS1 9
#define CPS1 70
// GEMM2: 40 m-tiles (5120 rows), Ksplit 7 (90 chunks/split, last 85)
#define MT2 40
#define MR2 5120
#define KS2 7
#define CPS2 90

#define BPITCH 40   // fp16 elems per B smem row (80B, conflict-free ldmatrix)

// ---------------- device scratch (static; no allocations) ----------------
__device__ float  g_px[NV * Bz];            // [v*32 + b]
__device__ float  g_py[NV * Bz];
__device__ float  g_pz[NV * Bz];
__device__ __half g_Bh[NT * Bz];            // B fp16, rows k-permuted per 16
__device__ float  g_cy[N1c * Bz];           // coeffy [i*32 + b]
__device__ float  g_cz[N12c * Bz];
__device__ float  g_Pf[(size_t)KS1 * MR1 * 32];  // K-split partial slab
__device__ float  g_vol[Bz];                // per-batch volume (atomic)
__device__ float  g_volc[1];                // base-mesh volume (atomic)
__device__ float  g_sy[Bz];
__device__ float  g_sz[Bz];

// k-permutation within each 16-group: physical pair q -> logical pair
// (q even ? q/2 : 4 + q/2). Makes A float4 halves = MMA a01/a45 directly.
__device__ __forceinline__ int kperm(int p) {
    int q = p >> 1;
    int lp = (q & 1) ? 4 + (q >> 1) : (q >> 1);
    return lp * 2 + (p & 1);
}

__device__ __forceinline__ uint32_t packh2(float a, float b) {
    __half2 h = __floats2half2_rn(a, b);
    return *(uint32_t*)&h;
}

// ---------------- K0: build SoA points (batch-fastest) + zero sums --------
__global__ void k_init(const float* __restrict__ x, const float* __restrict__ y,
                       const float* __restrict__ p0) {
    int u = blockIdx.x * 256 + threadIdx.x;
    if (u < 128) {
        if (u < 32) g_sy[u] = 0.f;
        else if (u < 64) g_sz[u - 32] = 0.f;
        else if (u < 96) g_vol[u - 64] = 0.f;
        else if (u == 96) g_volc[0] = 0.f;
    }
    if (u >= NV * Bz) return;
    int v = u >> 5, b = u & 31;
    float px, py, pz;
    if (v < N1c) {
        const float* xb = x + (size_t)b * (N1c * 3) + v * 3;
        px = xb[0]; py = xb[1]; pz = xb[2];
    } else if (v < N12c) {
        int j = v - N1c;
        const float* yb = y + (size_t)b * (N2c * 2) + j * 2;
        px = yb[0]; pz = yb[1]; py = p0[v * 3 + 1];
    } else {
        px = p0[v * 3]; py = p0[v * 3 + 1]; pz = p0[v * 3 + 2];
    }
    g_px[u] = px; g_py[u] = py; g_pz[u] = pz;
}

// ---------------- K1: per-triangle dets -> fp16 B (permuted rows) ---------
// phase 1 reads py WITH the rank-1 y-correction applied on the fly
__global__ void k_det(const int* __restrict__ tri, const float* __restrict__ p0,
                      int phase) {
    __shared__ float2 sv[16];
    __shared__ float  sc;
    int tid = threadIdx.x;
    if (phase == 0) {
        if (tid < 16) sv[tid] = make_float2(0.f, 0.f);
        if (tid == 0) sc = 0.f;
        __syncthreads();
    }
    int u = blockIdx.x * 256 + tid;
    int t = u >> 4, b2 = u & 15;
    if (t < NT) {
        int v0 = tri[t * 3], v1 = tri[t * 3 + 1], v2 = tri[t * 3 + 2];
        const float2* PX = (const float2*)g_px;
        const float2* PY = (const float2*)g_py;
        const float2* PZ = (const float2*)g_pz;
        float2 x0 = PX[v0 * 16 + b2], x1 = PX[v1 * 16 + b2], x2 = PX[v2 * 16 + b2];
        float2 d;
        if (phase == 0) {
            float2 z0 = PZ[v0 * 16 + b2], z1 = PZ[v1 * 16 + b2], z2 = PZ[v2 * 16 + b2];
            float2 y0 = PY[v0 * 16 + b2], y1 = PY[v1 * 16 + b2], y2 = PY[v2 * 16 + b2];
            d.x = ((x0.x - x1.x) * (z2.x - z1.x) - (z0.x - z1.x) * (x2.x - x1.x)) * (1.f / 6.f);
            d.y = ((x0.y - x1.y) * (z2.y - z1.y) - (z0.y - z1.y) * (x2.y - x1.y)) * (1.f / 6.f);
            atomicAdd(&sv[b2].x, (y0.x + y1.x + y2.x) * d.x);
            atomicAdd(&sv[b2].y, (y0.y + y1.y + y2.y) * d.y);
            if (b2 == 0) {
                float X0 = p0[v0 * 3], Y0 = p0[v0 * 3 + 1], Z0 = p0[v0 * 3 + 2];
                float X1 = p0[v1 * 3], Y1 = p0[v1 * 3 + 1], Z1 = p0[v1 * 3 + 2];
                float X2 = p0[v2 * 3], Y2 = p0[v2 * 3 + 1], Z2 = p0[v2 * 3 + 2];
                float d0 = ((X0 - X1) * (Z2 - Z1) - (Z0 - Z1) * (X2 - X1)) * (1.f / 6.f);
                atomicAdd(&sc, (Y0 + Y1 + Y2) * d0);
            }
        } else {
            float2 vv = ((const float2*)g_vol)[b2];
            float  vc = g_volc[0];
            float2 sy = ((const float2*)g_sy)[b2];
            float2 rat = make_float2(0.5f * (vc - vv.x) / sy.x,
                                     0.5f * (vc - vv.y) / sy.y);
            float2 y0 = PY[v0 * 16 + b2], y1 = PY[v1 * 16 + b2], y2 = PY[v2 * 16 + b2];
            if (v0 < N1c) { float2 c = *(const float2*)(g_cy + v0 * 32 + 2 * b2);
                            y0.x += c.x * rat.x; y0.y += c.y * rat.y; }
            if (v1 < N1c) { float2 c = *(const float2*)(g_cy + v1 * 32 + 2 * b2);
                            y1.x += c.x * rat.x; y1.y += c.y * rat.y; }
            if (v2 < N1c) { float2 c = *(const float2*)(g_cy + v2 * 32 + 2 * b2);
                            y2.x += c.x * rat.x; y2.y += c.y * rat.y; }
            d.x = ((x0.x - x2.x) * (y1.x - y2.x) - (y0.x - y2.x) * (x1.x - x2.x)) * (1.f / 6.f);
            d.y = ((x0.y - x2.y) * (y1.y - y2.y) - (y0.y - y2.y) * (x1.y - x2.y)) * (1.f / 6.f);
        }
        __half2 h = __floats2half2_rn(d.x, d.y);
        int tp = (t & ~15) | kperm(t & 15);   // permuted row for GEMM
        *(uint32_t*)(g_Bh + tp * 32 + 2 * b2) = *(uint32_t*)&h;
    }
    if (phase == 0) {
        __syncthreads();
        if (tid < 16) {
            atomicAdd(&g_vol[2 * tid],     sv[tid].x);
            atomicAdd(&g_vol[2 * tid + 1], sv[tid].y);
        }
        if (tid == 0) atomicAdd(&g_volc[0], sc);
    }
}

// ------- tensor-core GEMM: A fp16 single-term, B fp16 single-term ---------
#define LDSM4T(r, addr) \
    asm volatile("ldmatrix.sync.aligned.m8n8.x4.trans.shared.b16 {%0,%1,%2,%3}, [%4];" \
        : "=r"((r)[0]), "=r"((r)[1]), "=r"((r)[2]), "=r"((r)[3]) : "r"(addr))
#define MMAF16(dd, aa, bb) \
    asm volatile("mma.sync.aligned.m16n8k16.row.col.f32.f16.f16.f32 " \
        "{%0,%1,%2,%3}, {%4,%5,%6,%7}, {%8,%9}, {%0,%1,%2,%3};" \
        : "+f"((dd)[0]), "+f"((dd)[1]), "+f"((dd)[2]), "+f"((dd)[3]) \
        : "r"((aa)[0]), "r"((aa)[1]), "r"((aa)[2]), "r"((aa)[3]), \
          "r"((bb)[0]), "r"((bb)[1]))

__global__ void __launch_bounds__(256, 2)
k_gemm_tc(const float* __restrict__ A, int M, int Mrows, int cps) {
    __shared__ __align__(16) __half Bhs[4][32 * BPITCH];

    int tid = threadIdx.x;
    int lane = tid & 31, w = tid >> 5;      // 8 warps, each owns m16 rows
    int g = lane >> 2, t4 = lane & 3;
    int ibase = blockIdx.x * 128;
    int c0 = blockIdx.y * cps;
    int c1 = min(KC, c0 + cps);

    int row0 = ibase + w * 16 + g;
    bool v0 = row0 < M, v8 = (row0 + 8) < M;
    const float* A0 = A + (size_t)row0 * KKc + t4 * 4;
    const float* A8 = A0 + (size_t)8 * KKc;

    int bk = tid >> 3, bn = (tid & 7) * 4;  // B staging: 32 rows x 32 cols
    const size_t bOff = (size_t)bk * 32 + bn;

    // Two A chunk buffers, parity-static (selected by compile-time j&1).
    float4 arA[2][2], arB[2][2];            // [row r][kk]
    uint2 bhr[4];
    const float4 z4 = make_float4(0.f, 0.f, 0.f, 0.f);

#define LOADA(buf, c) do { \
        int _kb = (c) * 32; \
        buf[0][0] = v0 ? *(const float4*)(A0 + _kb)      : z4; \
        buf[0][1] = v0 ? *(const float4*)(A0 + _kb + 16) : z4; \
        buf[1][0] = v8 ? *(const float4*)(A8 + _kb)      : z4; \
        buf[1][1] = v8 ? *(const float4*)(A8 + _kb + 16) : z4; \
    } while (0)

    // prefetch A chunks c0 (parity 0) and c0+1 (parity 1)
    LOADA(arA, c0);
    if (c0 + 1 < c1) LOADA(arB, c0 + 1);
    // prefetch B group [c0, c0+4)
#pragma unroll
    for (int j = 0; j < 4; j++) {
        int c = c0 + j;
        if (c < c1)
            bhr[j] = *(const uint2*)(g_Bh + (size_t)c * 1024 + bOff);
    }

    float d[4][4];
#pragma unroll
    for (int nt = 0; nt < 4; nt++)
#pragma unroll
        for (int q = 0; q < 4; q++) d[nt][q] = 0.f;

    for (int cb = c0; cb < c1; cb += 4) {
        __syncthreads();
#pragma unroll
        for (int j = 0; j < 4; j++)
            if (cb + j < c1)
                *(uint2*)(&Bhs[j][bk * BPITCH + bn]) = bhr[j];
        __syncthreads();
        // prefetch next B group (flies during compute of this group)
#pragma unroll
        for (int j = 0; j < 4; j++) {
            int c = cb + 4 + j;
            if (c < c1)
                bhr[j] = *(const uint2*)(g_Bh + (size_t)c * 1024 + bOff);
        }
#pragma unroll
        for (int j = 0; j < 4; j++) {
            int c = cb + j;
            if (c >= c1) continue;
            // bind the parity buffer statically (j is a literal here)
            float4 (&ar)[2][2] = (j & 1) ? arB : arA;
            // A fragments: fp16 pack (float4 halves = a01/a45 via k-permuted B)
            uint32_t ahf[2][4];
#pragma unroll
            for (int kk = 0; kk < 2; kk++) {
                ahf[kk][0] = packh2(ar[0][kk].x, ar[0][kk].y);
                ahf[kk][1] = packh2(ar[1][kk].x, ar[1][kk].y);
                ahf[kk][2] = packh2(ar[0][kk].z, ar[0][kk].w);
                ahf[kk][3] = packh2(ar[1][kk].z, ar[1][kk].w);
            }
            // prefetch A chunk c+2 into the SAME parity buffer (2-deep)
            if (c + 2 < c1) LOADA(ar, c + 2);

            // B fragments via ldmatrix.x4.trans from slab j
            uint32_t bhB = (uint32_t)__cvta_generic_to_shared(&Bhs[j][0]);
#pragma unroll
            for (int kk = 0; kk < 2; kk++) {
                uint32_t bhf[4][2];
#pragma unroll
                for (int ntp = 0; ntp < 2; ntp++) {
                    int rrow = kk * 16 + (lane & 15);
                    int rcol = ntp * 16 + (lane >> 4) * 8;
                    uint32_t off = (uint32_t)(rrow * BPITCH + rcol) * 2;
                    uint32_t t[4];
                    LDSM4T(t, bhB + off);
                    bhf[ntp * 2][0] = t[0]; bhf[ntp * 2][1] = t[1];
                    bhf[ntp * 2 + 1][0] = t[2]; bhf[ntp * 2 + 1][1] = t[3];
                }
#pragma unroll
                for (int nt = 0; nt < 4; nt++) MMAF16(d[nt], ahf[kk], bhf[nt]);
            }
        }
    }
#undef LOADA

    float* slab = g_Pf + (size_t)blockIdx.y * Mrows * 32;
#pragma unroll
    for (int nt = 0; nt < 4; nt++) {
        int n = nt * 8 + t4 * 2;
        *(float2*)(slab + (size_t)row0 * 32 + n)       = make_float2(d[nt][0], d[nt][1]);
        *(float2*)(slab + (size_t)(row0 + 8) * 32 + n) = make_float2(d[nt][2], d[nt][3]);
    }
}

// ------- fold K-split partials -> coeff, s[b] = sum coeff^2 (unrolled) ----
template <int PHASE>
__global__ void k_reduce() {
    constexpr int Ksp   = PHASE ? KS2 : KS1;
    constexpr int Mrows = PHASE ? MR2 : MR1;
    constexpr int M     = PHASE ? N12c : N1c;
    __shared__ float sAcc[32];
    int tid = threadIdx.x;
    if (tid < 32) sAcc[tid] = 0.f;
    __syncthreads();
    float* coeff = PHASE ? g_cz : g_cy;
    float* sOut  = PHASE ? g_sz : g_sy;
    int u = blockIdx.x * 256 + tid;
    int b = u & 31;
    if (u < M * 32) {
        float s = 0.f;
#pragma unroll
        for (int j = 0; j < Ksp; j++) s += g_Pf[(size_t)j * Mrows * 32 + u];
        coeff[u] = s;
        atomicAdd(&sAcc[b], s * s);
    }
    __syncthreads();
    if (tid < 32) atomicAdd(&sOut[tid], sAcc[tid]);
}

// ------------- final outputs (y & z corrections applied on the fly) -------
__global__ void k_out(float* __restrict__ out) {
    int u = blockIdx.x * 256 + threadIdx.x;
    if (u >= N12c * Bz) return;
    int v = u >> 5, b = u & 31;
    float a = 0.5f * (g_volc[0] - g_vol[b]);
    float corr = g_cz[u] * (a / g_sz[b]);
    float X = g_px[u], Z = g_pz[u] + corr;
    if (v < N1c) {
        float Yv = g_py[u] + g_cy[u] * (a / g_sy[b]);
        float* o = out + (size_t)b * (N1c * 3) + v * 3;
        o[0] = X; o[1] = Yv; o[2] = Z;
    } else {
        int j = v - N1c;
        float* o = out + (size_t)Bz * N1c * 3 + (size_t)b * (N2c * 2) + j * 2;
        o[0] = X; o[1] = Z;
    }
}

extern "C" void kernel_launch(void* const* d_in, const int* in_sizes, int n_in,
                              void* d_out, int out_size) {
    const float* x   = (const float*)d_in[0];
    const float* y   = (const float*)d_in[1];
    const float* p0  = (const float*)d_in[2];
    const int*   tri = (const int*)d_in[3];
    const float* Vx  = (const float*)d_in[6];
    const float* Vxy = (const float*)d_in[7];
    float* out = (float*)d_out;
    (void)in_sizes; (void)n_in; (void)out_size;

    k_init<<<1500, 256>>>(x, y, p0);
    k_det<<<1250, 256>>>(tri, p0, 0);
    k_gemm_tc<<<dim3(MT1, KS1), 256>>>(Vx, N1c, MR1, CPS1);
    k_reduce<0><<<500, 256>>>();
    k_det<<<1250, 256>>>(tri, p0, 1);
    k_gemm_tc<<<dim3(MT2, KS2), 256>>>(Vxy, N12c, MR2, CPS2);
    k_reduce<1><<<625, 256>>>();
    k_out<<<625, 256>>>(out);
}

// round 16
// speedup vs baseline: 1.2341x; 1.1184x over previous
#include <cuda_runtime.h>
#include <cuda_fp16.h>
#include <cstdint>

#define Bz   32
#define NV   12000
#define NT   20000
#define N1c  4000
#define N2c  1000
#define N12c 5000
#define KKc  20000
#define KC   625            // 32-wide k-chunks (625*32 = 20000 exactly)

// GEMM1: 32 m-tiles (4096 rows), Ksplit 9 (72 chunks/split, last 49)
#define MT1 32
#define MR1 4096
#define KS1 9
#define CPS1 72
// GEMM2: 40 m-tiles (5120 rows), Ksplit 7 (90 chunks/split, last 85)
#define MT2 40
#define MR2 5120
#define KS2 7
#define CPS2 90

#define BPITCH 40   // fp16 elems per B smem row (80B, conflict-free ldmatrix)

// ---------------- device scratch (static; no allocations) ----------------
__device__ float  g_px[NV * Bz];            // [v*32 + b]
__device__ float  g_py[NV * Bz];
__device__ float  g_pz[NV * Bz];
__device__ __half g_Bh[NT * Bz];            // B fp16, rows k-permuted per 16
__device__ float  g_cy[N1c * Bz];           // coeffy [i*32 + b]
__device__ float  g_cz[N12c * Bz];
__device__ float  g_Pf[(size_t)KS1 * MR1 * 32];  // K-split partial slab
__device__ float  g_vol[Bz];                // per-batch volume (atomic)
__device__ float  g_volc[1];                // base-mesh volume (atomic)
__device__ float  g_sy[Bz];
__device__ float  g_sz[Bz];

// k-permutation within each 16-group: physical pair q -> logical pair
// (q even ? q/2 : 4 + q/2). Makes A float4 halves = MMA a01/a45 directly.
__device__ __forceinline__ int kperm(int p) {
    int q = p >> 1;
    int lp = (q & 1) ? 4 + (q >> 1) : (q >> 1);
    return lp * 2 + (p & 1);
}

__device__ __forceinline__ uint32_t packh2(float a, float b) {
    __half2 h = __floats2half2_rn(a, b);
    return *(uint32_t*)&h;
}

// ---------------- K0: build SoA points (batch-fastest) + zero sums --------
__global__ void k_init(const float* __restrict__ x, const float* __restrict__ y,
                       const float* __restrict__ p0) {
    int u = blockIdx.x * 256 + threadIdx.x;
    if (u < 128) {
        if (u < 32) g_sy[u] = 0.f;
        else if (u < 64) g_sz[u - 32] = 0.f;
        else if (u < 96) g_vol[u - 64] = 0.f;
        else if (u == 96) g_volc[0] = 0.f;
    }
    if (u >= NV * Bz) return;
    int v = u >> 5, b = u & 31;
    float px, py, pz;
    if (v < N1c) {
        const float* xb = x + (size_t)b * (N1c * 3) + v * 3;
        px = xb[0]; py = xb[1]; pz = xb[2];
    } else if (v < N12c) {
        int j = v - N1c;
        const float* yb = y + (size_t)b * (N2c * 2) + j * 2;
        px = yb[0]; pz = yb[1]; py = p0[v * 3 + 1];
    } else {
        px = p0[v * 3]; py = p0[v * 3 + 1]; pz = p0[v * 3 + 2];
    }
    g_px[u] = px; g_py[u] = py; g_pz[u] = pz;
}

// ---------------- K1: per-triangle dets -> fp16 B (permuted rows) ---------
// phase 1 reads py WITH the rank-1 y-correction applied on the fly
__global__ void k_det(const int* __restrict__ tri, const float* __restrict__ p0,
                      int phase) {
    __shared__ float2 sv[16];
    __shared__ float  sc;
    int tid = threadIdx.x;
    if (phase == 0) {
        if (tid < 16) sv[tid] = make_float2(0.f, 0.f);
        if (tid == 0) sc = 0.f;
        __syncthreads();
    }
    int u = blockIdx.x * 256 + tid;
    int t = u >> 4, b2 = u & 15;
    if (t < NT) {
        int v0 = tri[t * 3], v1 = tri[t * 3 + 1], v2 = tri[t * 3 + 2];
        const float2* PX = (const float2*)g_px;
        const float2* PY = (const float2*)g_py;
        const float2* PZ = (const float2*)g_pz;
        float2 x0 = PX[v0 * 16 + b2], x1 = PX[v1 * 16 + b2], x2 = PX[v2 * 16 + b2];
        float2 d;
        if (phase == 0) {
            float2 z0 = PZ[v0 * 16 + b2], z1 = PZ[v1 * 16 + b2], z2 = PZ[v2 * 16 + b2];
            float2 y0 = PY[v0 * 16 + b2], y1 = PY[v1 * 16 + b2], y2 = PY[v2 * 16 + b2];
            d.x = ((x0.x - x1.x) * (z2.x - z1.x) - (z0.x - z1.x) * (x2.x - x1.x)) * (1.f / 6.f);
            d.y = ((x0.y - x1.y) * (z2.y - z1.y) - (z0.y - z1.y) * (x2.y - x1.y)) * (1.f / 6.f);
            atomicAdd(&sv[b2].x, (y0.x + y1.x + y2.x) * d.x);
            atomicAdd(&sv[b2].y, (y0.y + y1.y + y2.y) * d.y);
            if (b2 == 0) {
                float X0 = p0[v0 * 3], Y0 = p0[v0 * 3 + 1], Z0 = p0[v0 * 3 + 2];
                float X1 = p0[v1 * 3], Y1 = p0[v1 * 3 + 1], Z1 = p0[v1 * 3 + 2];
                float X2 = p0[v2 * 3], Y2 = p0[v2 * 3 + 1], Z2 = p0[v2 * 3 + 2];
                float d0 = ((X0 - X1) * (Z2 - Z1) - (Z0 - Z1) * (X2 - X1)) * (1.f / 6.f);
                atomicAdd(&sc, (Y0 + Y1 + Y2) * d0);
            }
        } else {
            float2 vv = ((const float2*)g_vol)[b2];
            float  vc = g_volc[0];
            float2 sy = ((const float2*)g_sy)[b2];
            float2 rat = make_float2(0.5f * (vc - vv.x) / sy.x,
                                     0.5f * (vc - vv.y) / sy.y);
            float2 y0 = PY[v0 * 16 + b2], y1 = PY[v1 * 16 + b2], y2 = PY[v2 * 16 + b2];
            if (v0 < N1c) { float2 c = *(const float2*)(g_cy + v0 * 32 + 2 * b2);
                            y0.x += c.x * rat.x; y0.y += c.y * rat.y; }
            if (v1 < N1c) { float2 c = *(const float2*)(g_cy + v1 * 32 + 2 * b2);
                            y1.x += c.x * rat.x; y1.y += c.y * rat.y; }
            if (v2 < N1c) { float2 c = *(const float2*)(g_cy + v2 * 32 + 2 * b2);
                            y2.x += c.x * rat.x; y2.y += c.y * rat.y; }
            d.x = ((x0.x - x2.x) * (y1.x - y2.x) - (y0.x - y2.x) * (x1.x - x2.x)) * (1.f / 6.f);
            d.y = ((x0.y - x2.y) * (y1.y - y2.y) - (y0.y - y2.y) * (x1.y - x2.y)) * (1.f / 6.f);
        }
        __half2 h = __floats2half2_rn(d.x, d.y);
        int tp = (t & ~15) | kperm(t & 15);   // permuted row for GEMM
        *(uint32_t*)(g_Bh + tp * 32 + 2 * b2) = *(uint32_t*)&h;
    }
    if (phase == 0) {
        __syncthreads();
        if (tid < 16) {
            atomicAdd(&g_vol[2 * tid],     sv[tid].x);
            atomicAdd(&g_vol[2 * tid + 1], sv[tid].y);
        }
        if (tid == 0) atomicAdd(&g_volc[0], sc);
    }
}

// -- tensor-core GEMM: A LDG.128 3-deep (static buffers), B 3-slab smem ----
#define LDSM4T(r, addr) \
    asm volatile("ldmatrix.sync.aligned.m8n8.x4.trans.shared.b16 {%0,%1,%2,%3}, [%4];" \
        : "=r"((r)[0]), "=r"((r)[1]), "=r"((r)[2]), "=r"((r)[3]) : "r"(addr))
#define MMAF16(dd, aa, bb) \
    asm volatile("mma.sync.aligned.m16n8k16.row.col.f32.f16.f16.f32 " \
        "{%0,%1,%2,%3}, {%4,%5,%6,%7}, {%8,%9}, {%0,%1,%2,%3};" \
        : "+f"((dd)[0]), "+f"((dd)[1]), "+f"((dd)[2]), "+f"((dd)[3]) \
        : "r"((aa)[0]), "r"((aa)[1]), "r"((aa)[2]), "r"((aa)[3]), \
          "r"((bb)[0]), "r"((bb)[1]))

__global__ void __launch_bounds__(256, 2)
k_gemm_tc(const float* __restrict__ A, int M, int Mrows, int cps) {
    __shared__ __align__(16) __half Bhs[3][32 * BPITCH];

    int tid = threadIdx.x;
    int lane = tid & 31, w = tid >> 5;      // 8 warps, each owns m16 rows
    int g = lane >> 2, t4 = lane & 3;
    int ibase = blockIdx.x * 128;
    int c0 = blockIdx.y * cps;
    int c1 = min(KC, c0 + cps);

    int row0 = ibase + w * 16 + g;
    bool v0 = row0 < M, v8 = (row0 + 8) < M;
    const float* A0 = A + (size_t)row0 * KKc + t4 * 4;
    const float* A8 = A0 + (size_t)8 * KKc;

    int bk = tid >> 3, bn = (tid & 7) * 4;  // B staging: 32 rows x 32 cols
    const size_t bOff = (size_t)bk * 32 + bn;

    // Three A chunk buffers, statically selected by literal j in {0,1,2}.
    float4 arA[2][2], arB[2][2], arC[2][2]; // [row r][kk]
    uint2 bhr[3];
    const float4 z4 = make_float4(0.f, 0.f, 0.f, 0.f);

#define LOADA(buf, c) do { \
        int _kb = (c) * 32; \
        buf[0][0] = v0 ? *(const float4*)(A0 + _kb)      : z4; \
        buf[0][1] = v0 ? *(const float4*)(A0 + _kb + 16) : z4; \
        buf[1][0] = v8 ? *(const float4*)(A8 + _kb)      : z4; \
        buf[1][1] = v8 ? *(const float4*)(A8 + _kb + 16) : z4; \
    } while (0)

    // prefetch A chunks c0..c0+2 (3-deep)
    LOADA(arA, c0);
    if (c0 + 1 < c1) LOADA(arB, c0 + 1);
    if (c0 + 2 < c1) LOADA(arC, c0 + 2);
    // prefetch B group [c0, c0+3)
#pragma unroll
    for (int j = 0; j < 3; j++) {
        int c = c0 + j;
        if (c < c1)
            bhr[j] = *(const uint2*)(g_Bh + (size_t)c * 1024 + bOff);
    }

    float d[4][4];
#pragma unroll
    for (int nt = 0; nt < 4; nt++)
#pragma unroll
        for (int q = 0; q < 4; q++) d[nt][q] = 0.f;

    for (int cb = c0; cb < c1; cb += 3) {
        __syncthreads();
#pragma unroll
        for (int j = 0; j < 3; j++)
            if (cb + j < c1)
                *(uint2*)(&Bhs[j][bk * BPITCH + bn]) = bhr[j];
        __syncthreads();
        // prefetch next B group (flies during compute of this group)
#pragma unroll
        for (int j = 0; j < 3; j++) {
            int c = cb + 3 + j;
            if (c < c1)
                bhr[j] = *(const uint2*)(g_Bh + (size_t)c * 1024 + bOff);
        }
#pragma unroll
        for (int j = 0; j < 3; j++) {
            int c = cb + j;
            if (c >= c1) continue;
            // bind the A buffer statically (j is a literal here)
            float4 (&ar)[2][2] = (j == 0) ? arA : (j == 1) ? arB : arC;
            // A fragments: fp16 pack (float4 halves = a01/a45 via k-permuted B)
            uint32_t ahf[2][4];
#pragma unroll
            for (int kk = 0; kk < 2; kk++) {
                ahf[kk][0] = packh2(ar[0][kk].x, ar[0][kk].y);
                ahf[kk][1] = packh2(ar[1][kk].x, ar[1][kk].y);
                ahf[kk][2] = packh2(ar[0][kk].z, ar[0][kk].w);
                ahf[kk][3] = packh2(ar[1][kk].z, ar[1][kk].w);
            }
            // prefetch A chunk c+3 into the SAME buffer (3-deep)
            if (c + 3 < c1) LOADA(ar, c + 3);

            // B fragments via ldmatrix.x4.trans from slab j
            uint32_t bhB = (uint32_t)__cvta_generic_to_shared(&Bhs[j][0]);
#pragma unroll
            for (int kk = 0; kk < 2; kk++) {
                uint32_t bhf[4][2];
#pragma unroll
                for (int ntp = 0; ntp < 2; ntp++) {
                    int rrow = kk * 16 + (lane & 15);
                    int rcol = ntp * 16 + (lane >> 4) * 8;
                    uint32_t off = (uint32_t)(rrow * BPITCH + rcol) * 2;
                    uint32_t t[4];
                    LDSM4T(t, bhB + off);
                    bhf[ntp * 2][0] = t[0]; bhf[ntp * 2][1] = t[1];
                    bhf[ntp * 2 + 1][0] = t[2]; bhf[ntp * 2 + 1][1] = t[3];
                }
#pragma unroll
                for (int nt = 0; nt < 4; nt++) MMAF16(d[nt], ahf[kk], bhf[nt]);
            }
        }
    }
#undef LOADA

    float* slab = g_Pf + (size_t)blockIdx.y * Mrows * 32;
#pragma unroll
    for (int nt = 0; nt < 4; nt++) {
        int n = nt * 8 + t4 * 2;
        *(float2*)(slab + (size_t)row0 * 32 + n)       = make_float2(d[nt][0], d[nt][1]);
        *(float2*)(slab + (size_t)(row0 + 8) * 32 + n) = make_float2(d[nt][2], d[nt][3]);
    }
}

// ------- fold K-split partials -> coeff, s[b] = sum coeff^2 (unrolled) ----
template <int PHASE>
__global__ void k_reduce() {
    constexpr int Ksp   = PHASE ? KS2 : KS1;
    constexpr int Mrows = PHASE ? MR2 : MR1;
    constexpr int M     = PHASE ? N12c : N1c;
    __shared__ float sAcc[32];
    int tid = threadIdx.x;
    if (tid < 32) sAcc[tid] = 0.f;
    __syncthreads();
    float* coeff = PHASE ? g_cz : g_cy;
    float* sOut  = PHASE ? g_sz : g_sy;
    int u = blockIdx.x * 256 + tid;
    int b = u & 31;
    if (u < M * 32) {
        float s = 0.f;
#pragma unroll
        for (int j = 0; j < Ksp; j++) s += g_Pf[(size_t)j * Mrows * 32 + u];
        coeff[u] = s;
        atomicAdd(&sAcc[b], s * s);
    }
    __syncthreads();
    if (tid < 32) atomicAdd(&sOut[tid], sAcc[tid]);
}

// ------------- final outputs (y & z corrections applied on the fly) -------
__global__ void k_out(float* __restrict__ out) {
    int u = blockIdx.x * 256 + threadIdx.x;
    if (u >= N12c * Bz) return;
    int v = u >> 5, b = u & 31;
    float a = 0.5f * (g_volc[0] - g_vol[b]);
    float corr = g_cz[u] * (a / g_sz[b]);
    float X = g_px[u], Z = g_pz[u] + corr;
    if (v < N1c) {
        float Yv = g_py[u] + g_cy[u] * (a / g_sy[b]);
        float* o = out + (size_t)b * (N1c * 3) + v * 3;
        o[0] = X; o[1] = Yv; o[2] = Z;
    } else {
        int j = v - N1c;
        float* o = out + (size_t)Bz * N1c * 3 + (size_t)b * (N2c * 2) + j * 2;
        o[0] = X; o[1] = Z;
    }
}

extern "C" void kernel_launch(void* const* d_in, const int* in_sizes, int n_in,
                              void* d_out, int out_size) {
    const float* x   = (const float*)d_in[0];
    const float* y   = (const float*)d_in[1];
    const float* p0  = (const float*)d_in[2];
    const int*   tri = (const int*)d_in[3];
    const float* Vx  = (const float*)d_in[6];
    const float* Vxy = (const float*)d_in[7];
    float* out = (float*)d_out;
    (void)in_sizes; (void)n_in; (void)out_size;

    k_init<<<1500, 256>>>(x, y, p0);
    k_det<<<1250, 256>>>(tri, p0, 0);
    k_gemm_tc<<<dim3(MT1, KS1), 256>>>(Vx, N1c, MR1, CPS1);
    k_reduce<0><<<500, 256>>>();
    k_det<<<1250, 256>>>(tri, p0, 1);
    k_gemm_tc<<<dim3(MT2, KS2), 256>>>(Vxy, N12c, MR2, CPS2);
    k_reduce<1><<<625, 256>>>();
    k_out<<<625, 256>>>(out);
}